// round 15
// baseline (speedup 1.0000x reference)
#include <cuda_runtime.h>
#include <cuda_bf16.h>
#include <stdint.h>

// Problem constants (fixed by the dataset)
#define MAXN 50000
#define MAXE 500000
#define DIN  128

// packed fp32x2 FMA (sm_103a): d = a*b + d, elementwise on 2 packed fp32 lanes.
// ptxas never auto-generates FFMA2; PTX-only -> 2x fp32 FMA throughput.
#define FMA2(d, a, b) asm("fma.rn.f32x2 %0, %1, %2, %0;" : "+l"(d) : "l"(a), "l"(b))
#define DUP2(out, w)  asm("mov.b64 %0, {%1, %1};" : "=l"(out) : "r"(w))

// ---------------- scratch (device globals; no allocation allowed) ----------------
__device__ __align__(16) float g_Hs[(size_t)MAXN * 128];   // X@W1 (UNSCALED)
__device__ __align__(16) float g_Gs[(size_t)MAXN * 64];    // (relu(L1)@W2)*dinv
__device__ int   g_cnt[MAXN];                // in-degree (no self loop)
__device__ int   g_fill[MAXN];               // bucket fill cursors
__device__ int   g_rowptr[MAXN + 1];         // CSR row pointers (by dst)
__device__ int   g_srcs[MAXE];               // CSR column (src) indices
__device__ float g_dinv[MAXN];               // 1/sqrt(deg), deg = indeg+1
__device__ int   g_bsum[128];                // scan block sums

// ---------------- preprocessing ----------------
// edge_index is int32 (JAX x64 disabled)
__global__ void k_count(const int* __restrict__ ei, int E, int n) {
    int e = blockIdx.x * blockDim.x + threadIdx.x;
    if (e < E) {
        int d = ei[E + e];
        if ((unsigned)d < (unsigned)n)
            atomicAdd(&g_cnt[d], 1);
    }
}

// exclusive scan, 512 elements per block; block sums to g_bsum
__global__ void k_scan1(int n) {
    __shared__ int sh[512];
    int i = blockIdx.x * 512 + threadIdx.x;
    int v = (i < n) ? g_cnt[i] : 0;
    sh[threadIdx.x] = v;
    __syncthreads();
    for (int off = 1; off < 512; off <<= 1) {
        int t = 0;
        if ((int)threadIdx.x >= off) t = sh[threadIdx.x - off];
        __syncthreads();
        sh[threadIdx.x] += t;
        __syncthreads();
    }
    int incl = sh[threadIdx.x];
    if (i < n) g_rowptr[i] = incl - v;       // block-local exclusive
    if (threadIdx.x == 511) g_bsum[blockIdx.x] = incl;
}

// fused: per-block redundant reduction of bsum[0..bid-1] (<=98 elems),
// then finalize rowptr + dinv.
__global__ void k_scan3f(int n) {
    __shared__ int sh[16];
    const int bid = blockIdx.x;
    const int t = threadIdx.x;

    int p = (t < bid) ? g_bsum[t] : 0;       // bid <= 97 < 512
    #pragma unroll
    for (int o = 16; o; o >>= 1) p += __shfl_down_sync(0xFFFFFFFFu, p, o);
    if ((t & 31) == 0) sh[t >> 5] = p;
    __syncthreads();
    if (t < 32) {
        int v = (t < 16) ? sh[t] : 0;
        #pragma unroll
        for (int o = 8; o; o >>= 1) v += __shfl_down_sync(0xFFFFFFFFu, v, o);
        if (t == 0) sh[0] = v;
    }
    __syncthreads();
    const int boff = sh[0];

    int i = bid * 512 + t;
    if (i < n) {
        int rp = g_rowptr[i] + boff;
        g_rowptr[i] = rp;
        g_dinv[i] = rsqrtf((float)(g_cnt[i] + 1));
        if (i == n - 1) g_rowptr[n] = rp + g_cnt[i];
    }
}

__global__ void k_fill(const int* __restrict__ ei, int E, int n) {
    int e = blockIdx.x * blockDim.x + threadIdx.x;
    if (e < E) {
        int s = ei[e];
        int d = ei[E + e];
        if ((unsigned)s < (unsigned)n && (unsigned)d < (unsigned)n) {
            int pos = g_rowptr[d] + atomicAdd(&g_fill[d], 1);
            g_srcs[pos] = s;
        }
    }
}

// ---------------- GEMM layer 1: g_Hs = x @ W1 (UNSCALED) ----------------
// Node-pair-packed fma.rn.f32x2 accumulators: 32 FFMA2 per k per thread.
// Runs concurrently with the CSR build (needs only x, W1).
__global__ void __launch_bounds__(256, 2) k_gemm1(const float* __restrict__ Xin,
                                                  const float* __restrict__ W, int n) {
    constexpr int F   = 128;
    constexpr int CG  = F / 8;          // 16 column groups (8 cols each)
    constexpr int NG  = 256 / CG;       // 16 node groups
    constexpr int NPT = 8;              // nodes per thread (4 packed pairs)
    constexpr int NB  = NG * NPT;       // 128 nodes per block
    constexpr int KC  = 32;             // k-chunk
    constexpr int NBP = NB + 4;

    __shared__ __align__(16) float sW[KC][F];
    __shared__ __align__(16) float sX[KC][NBP];

    const int tid = threadIdx.x;
    const int cg  = tid % CG;
    const int ng  = tid / CG;
    const int node0 = blockIdx.x * NB;

    unsigned long long acc[4][8];
    #pragma unroll
    for (int p = 0; p < 4; p++)
        #pragma unroll
        for (int c = 0; c < 8; c++) acc[p][c] = 0ull;

    for (int k0 = 0; k0 < DIN; k0 += KC) {
        {
            const float4* wsrc = (const float4*)(W + (size_t)k0 * F);
            float4* wdst = (float4*)&sW[0][0];
            #pragma unroll
            for (int i = tid; i < KC * F / 4; i += 256) wdst[i] = wsrc[i];
        }
        #pragma unroll
        for (int i = tid; i < NB * KC / 4; i += 256) {
            int r = i / (KC / 4);
            int c = i % (KC / 4);
            int node = node0 + r;
            float4 v = make_float4(0.f, 0.f, 0.f, 0.f);
            if (node < n) v = *(const float4*)(Xin + (size_t)node * DIN + k0 + c * 4);
            sX[c * 4 + 0][r] = v.x;
            sX[c * 4 + 1][r] = v.y;
            sX[c * 4 + 2][r] = v.z;
            sX[c * 4 + 3][r] = v.w;
        }
        __syncthreads();

        #pragma unroll
        for (int k = 0; k < KC; k++) {
            const float4 wa = *(const float4*)&sW[k][cg * 8];
            const float4 wb = *(const float4*)&sW[k][cg * 8 + 4];
            unsigned long long wd[8];
            DUP2(wd[0], __float_as_uint(wa.x)); DUP2(wd[1], __float_as_uint(wa.y));
            DUP2(wd[2], __float_as_uint(wa.z)); DUP2(wd[3], __float_as_uint(wa.w));
            DUP2(wd[4], __float_as_uint(wb.x)); DUP2(wd[5], __float_as_uint(wb.y));
            DUP2(wd[6], __float_as_uint(wb.z)); DUP2(wd[7], __float_as_uint(wb.w));
            const ulonglong2 xA = *(const ulonglong2*)&sX[k][ng * NPT];
            const ulonglong2 xB = *(const ulonglong2*)&sX[k][ng * NPT + 4];
            const unsigned long long xp[4] = { xA.x, xA.y, xB.x, xB.y };
            #pragma unroll
            for (int p = 0; p < 4; p++)
                #pragma unroll
                for (int c = 0; c < 8; c++)
                    FMA2(acc[p][c], xp[p], wd[c]);
        }
        __syncthreads();
    }

    #pragma unroll
    for (int p = 0; p < 4; p++) {
        float2 c0 = *(float2*)&acc[p][0], c1 = *(float2*)&acc[p][1];
        float2 c2 = *(float2*)&acc[p][2], c3 = *(float2*)&acc[p][3];
        float2 c4 = *(float2*)&acc[p][4], c5 = *(float2*)&acc[p][5];
        float2 c6 = *(float2*)&acc[p][6], c7 = *(float2*)&acc[p][7];
        int ne = node0 + ng * NPT + 2 * p;
        if (ne < n) {
            float* o = g_Hs + (size_t)ne * F + cg * 8;
            *(float4*)(o)     = make_float4(c0.x, c1.x, c2.x, c3.x);
            *(float4*)(o + 4) = make_float4(c4.x, c5.x, c6.x, c7.x);
        }
        if (ne + 1 < n) {
            float* o = g_Hs + (size_t)(ne + 1) * F + cg * 8;
            *(float4*)(o)     = make_float4(c0.y, c1.y, c2.y, c3.y);
            *(float4*)(o + 4) = make_float4(c4.y, c5.y, c6.y, c7.y);
        }
    }
}

// ---------------- FUSED agg1 + gemm2 ----------------
// Per node i (one warp):
//   h1 = relu( dinv_i*( sum_e Hs[s]*dinv[s] + Hs[i]*dinv[i] ) + b1 )   [regs]
//   Gs[i] = (h1 @ W2) * dinv_i                                          [FFMA2]
// h1 never touches gmem. W2 staged in smem (32KB); h1 staged per-warp (16KB).
// GEMM FMA work hides under the L2 gather latency of the next warps.
__global__ void __launch_bounds__(1024, 1) k_agg1g2(const float* __restrict__ bias,
                                                    const float* __restrict__ W2, int n) {
    __shared__ __align__(16) float sW2[128][64];   // 32 KB, row-major [k][c]
    __shared__ __align__(16) float sH[32][128];    // 16 KB, per-warp h1 staging

    const int tid  = threadIdx.x;
    const int wid  = tid >> 5;
    const int lane = tid & 31;
    const int w    = blockIdx.x * 32 + wid;        // node id

    // stage W2 (all threads; must precede the one __syncthreads)
    {
        const float4* src = (const float4*)W2;
        float4* dst = (float4*)&sW2[0][0];
        #pragma unroll
        for (int i = tid; i < 128 * 64 / 4; i += 1024) dst[i] = src[i];
    }
    __syncthreads();

    const bool active = (w < n);
    float dv = 0.f;
    float4 a = make_float4(0.f, 0.f, 0.f, 0.f);

    if (active) {
        const int beg = g_rowptr[w];
        const int end = g_rowptr[w + 1];
        dv = g_dinv[w];

        const float4* __restrict__ H4 = (const float4*)g_Hs;
        float4 hs = H4[(size_t)w * 32 + lane];
        a = make_float4(hs.x * dv, hs.y * dv, hs.z * dv, hs.w * dv); // self: Hs[i]*dinv[i]
        int e = beg;
        for (; e + 3 < end; e += 4) {
            int s0 = g_srcs[e], s1 = g_srcs[e + 1], s2 = g_srcs[e + 2], s3 = g_srcs[e + 3];
            float d0 = g_dinv[s0], d1 = g_dinv[s1], d2 = g_dinv[s2], d3 = g_dinv[s3];
            float4 v0 = H4[(size_t)s0 * 32 + lane];
            float4 v1 = H4[(size_t)s1 * 32 + lane];
            float4 v2 = H4[(size_t)s2 * 32 + lane];
            float4 v3 = H4[(size_t)s3 * 32 + lane];
            a.x = fmaf(v0.x, d0, a.x); a.y = fmaf(v0.y, d0, a.y);
            a.z = fmaf(v0.z, d0, a.z); a.w = fmaf(v0.w, d0, a.w);
            a.x = fmaf(v1.x, d1, a.x); a.y = fmaf(v1.y, d1, a.y);
            a.z = fmaf(v1.z, d1, a.z); a.w = fmaf(v1.w, d1, a.w);
            a.x = fmaf(v2.x, d2, a.x); a.y = fmaf(v2.y, d2, a.y);
            a.z = fmaf(v2.z, d2, a.z); a.w = fmaf(v2.w, d2, a.w);
            a.x = fmaf(v3.x, d3, a.x); a.y = fmaf(v3.y, d3, a.y);
            a.z = fmaf(v3.z, d3, a.z); a.w = fmaf(v3.w, d3, a.w);
        }
        for (; e < end; e++) {
            int s = g_srcs[e];
            float ds = g_dinv[s];
            float4 v = H4[(size_t)s * 32 + lane];
            a.x = fmaf(v.x, ds, a.x); a.y = fmaf(v.y, ds, a.y);
            a.z = fmaf(v.z, ds, a.z); a.w = fmaf(v.w, ds, a.w);
        }

        // h1 (relu), stage into this warp's smem row
        float4 bb = ((const float4*)bias)[lane];
        float4 h;
        h.x = fmaxf(a.x * dv + bb.x, 0.f);
        h.y = fmaxf(a.y * dv + bb.y, 0.f);
        h.z = fmaxf(a.z * dv + bb.z, 0.f);
        h.w = fmaxf(a.w * dv + bb.w, 0.f);
        *(float4*)&sH[wid][lane * 4] = h;
    }
    __syncwarp();

    if (active) {
        // GEMM: this lane computes output cols (2*lane, 2*lane+1)
        unsigned long long acc = 0ull;
        #pragma unroll
        for (int kk = 0; kk < 32; kk++) {
            const float4 h4 = *(const float4*)&sH[wid][kk * 4];
            unsigned long long w0 = *(const unsigned long long*)&sW2[kk * 4 + 0][lane * 2];
            unsigned long long w1 = *(const unsigned long long*)&sW2[kk * 4 + 1][lane * 2];
            unsigned long long w2 = *(const unsigned long long*)&sW2[kk * 4 + 2][lane * 2];
            unsigned long long w3 = *(const unsigned long long*)&sW2[kk * 4 + 3][lane * 2];
            unsigned long long xd;
            DUP2(xd, __float_as_uint(h4.x)); FMA2(acc, xd, w0);
            DUP2(xd, __float_as_uint(h4.y)); FMA2(acc, xd, w1);
            DUP2(xd, __float_as_uint(h4.z)); FMA2(acc, xd, w2);
            DUP2(xd, __float_as_uint(h4.w)); FMA2(acc, xd, w3);
        }
        float2 g = *(float2*)&acc;
        g.x *= dv; g.y *= dv;
        *(float2*)&g_Gs[(size_t)w * 64 + lane * 2] = g;
    }
}

// ---------------- aggregation layer 2: out = dinv*(gather + self) + b2 ----------------
// Gs is dinv-scaled already; half-warp per node: 16 lanes x float4 = 64-float row
__global__ void k_agg2(const float* __restrict__ bias, float* __restrict__ Yout, int n) {
    const int hw = (blockIdx.x * blockDim.x + threadIdx.x) >> 4;
    const int l  = threadIdx.x & 15;
    if (hw >= n) return;

    const int beg = g_rowptr[hw];
    const int end = g_rowptr[hw + 1];
    const float dv = g_dinv[hw];

    const float4* __restrict__ G4 = (const float4*)g_Gs;
    float4 a = G4[(size_t)hw * 16 + l];   // self-loop term
    int e = beg;
    for (; e + 3 < end; e += 4) {
        int s0 = g_srcs[e], s1 = g_srcs[e + 1], s2 = g_srcs[e + 2], s3 = g_srcs[e + 3];
        float4 v0 = G4[(size_t)s0 * 16 + l];
        float4 v1 = G4[(size_t)s1 * 16 + l];
        float4 v2 = G4[(size_t)s2 * 16 + l];
        float4 v3 = G4[(size_t)s3 * 16 + l];
        a.x += v0.x + v1.x + v2.x + v3.x;
        a.y += v0.y + v1.y + v2.y + v3.y;
        a.z += v0.z + v1.z + v2.z + v3.z;
        a.w += v0.w + v1.w + v2.w + v3.w;
    }
    for (; e < end; e++) {
        int s = g_srcs[e];
        float4 v = G4[(size_t)s * 16 + l];
        a.x += v.x; a.y += v.y; a.z += v.z; a.w += v.w;
    }
    float4 bb = ((const float4*)bias)[l];
    float4 o;
    o.x = a.x * dv + bb.x;
    o.y = a.y * dv + bb.y;
    o.z = a.z * dv + bb.z;
    o.w = a.w * dv + bb.w;
    ((float4*)Yout)[(size_t)hw * 16 + l] = o;
}

// ---------------- launch ----------------
extern "C" void kernel_launch(void* const* d_in, const int* in_sizes, int n_in,
                              void* d_out, int out_size) {
    const float* x  = (const float*)d_in[0];
    const int*   ei = (const int*)d_in[1];    // int32 (JAX x64 disabled)
    const float* W1 = (const float*)d_in[2];
    const float* b1 = (const float*)d_in[3];
    const float* W2 = (const float*)d_in[4];
    const float* b2 = (const float*)d_in[5];
    float*       out = (float*)d_out;

    const int n = in_sizes[0] / 128;   // 50000
    const int E = in_sizes[1] / 2;     // 500000
    const int nb = (n + 511) / 512;    // 98

    // One-time host resources (no device allocation; identical work every call).
    static cudaStream_t s2 = nullptr;
    static cudaEvent_t evFork = nullptr, evJoin = nullptr;
    static void *p_cnt = nullptr, *p_fill = nullptr;
    if (!s2) {
        cudaStreamCreateWithFlags(&s2, cudaStreamNonBlocking);
        cudaEventCreateWithFlags(&evFork, cudaEventDisableTiming);
        cudaEventCreateWithFlags(&evJoin, cudaEventDisableTiming);
        cudaGetSymbolAddress(&p_cnt, g_cnt);
        cudaGetSymbolAddress(&p_fill, g_fill);
    }

    // ---- fork: gemm1 (needs only x, W1) runs concurrent with the CSR build ----
    cudaEventRecord(evFork, 0);
    cudaStreamWaitEvent(s2, evFork, 0);
    k_gemm1<<<(n + 127) / 128, 256, 0, s2>>>(x, W1, n);
    cudaEventRecord(evJoin, s2);

    // ---- CSR build chain (stream 0) ----
    cudaMemsetAsync(p_cnt, 0, (size_t)n * sizeof(int), 0);
    cudaMemsetAsync(p_fill, 0, (size_t)n * sizeof(int), 0);
    k_count<<<(E + 255) / 256, 256>>>(ei, E, n);
    k_scan1<<<nb, 512>>>(n);
    k_scan3f<<<nb, 512>>>(n);
    k_fill<<<(E + 255) / 256, 256>>>(ei, E, n);

    // ---- join, then fused layer-1 aggregation + layer-2 GEMM ----
    cudaStreamWaitEvent(0, evJoin, 0);
    k_agg1g2<<<(n + 31) / 32, 1024>>>(b1, W2, n);

    // ---- layer-2 aggregation ----
    k_agg2<<<(n + 15) / 16, 256>>>(b2, out, n);
}